// round 4
// baseline (speedup 1.0000x reference)
#include <cuda_runtime.h>
#include <cuda_fp16.h>
#include <cstdint>

#define NTOK 2048
#define NG   32
#define DIN  1024
#define DHID 2048
#define DOUT 1024

// ---------------- scratch ----------------
__device__ __align__(1024) __half g_wA[(size_t)NG * 2 * DHID * DIN];   // [g][2h+s][k]  (s=0 gate, 1 up)
__device__ __align__(1024) __half g_wD[(size_t)NG * DOUT * DHID];      // [g][o][h]
__device__ __align__(1024) __half g_x16[(size_t)NTOK * NG * DIN];      // fp16 x
__device__ __align__(1024) __half g_hid[(size_t)NTOK * NG * DHID];     // fp16 hidden

// ---------------- PTX helpers ----------------
static __device__ __forceinline__ uint32_t smem_u32(const void* p) {
    uint32_t a;
    asm("{ .reg .u64 t; cvta.to.shared.u64 t, %1; cvt.u32.u64 %0, t; }" : "=r"(a) : "l"(p));
    return a;
}
#define CP_ASYNC16(dst, src) \
    asm volatile("cp.async.cg.shared.global [%0], [%1], 16;" :: "r"(dst), "l"(src))
#define CP_COMMIT() asm volatile("cp.async.commit_group;" ::: "memory")
#define CP_WAIT1()  asm volatile("cp.async.wait_group 1;" ::: "memory")

static __device__ __forceinline__ void ldsm4(uint32_t* r, uint32_t addr) {
    asm volatile("ldmatrix.sync.aligned.m8n8.x4.shared.b16 {%0,%1,%2,%3}, [%4];"
                 : "=r"(r[0]), "=r"(r[1]), "=r"(r[2]), "=r"(r[3]) : "r"(addr));
}
static __device__ __forceinline__ void mma16816(float* c, const uint32_t* a,
                                                uint32_t b0, uint32_t b1) {
    asm volatile(
        "mma.sync.aligned.m16n8k16.row.col.f32.f16.f16.f32 "
        "{%0,%1,%2,%3}, {%4,%5,%6,%7}, {%8,%9}, {%0,%1,%2,%3};"
        : "+f"(c[0]), "+f"(c[1]), "+f"(c[2]), "+f"(c[3])
        : "r"(a[0]), "r"(a[1]), "r"(a[2]), "r"(a[3]), "r"(b0), "r"(b1));
}

// ---------------- prepass kernels (unchanged, proven) ----------------
__global__ void prep_gateup(const float* __restrict__ gw, const float* __restrict__ uw) {
    __shared__ float tg[32][33];
    __shared__ float tu[32][33];
    int g = blockIdx.z, k0 = blockIdx.x * 32, h0 = blockIdx.y * 32;
    int tx = threadIdx.x, ty = threadIdx.y;
    const float* gp = gw + ((size_t)g * DIN + k0) * DHID + h0;
    const float* up = uw + ((size_t)g * DIN + k0) * DHID + h0;
#pragma unroll
    for (int i = 0; i < 4; ++i) {
        int k = ty + i * 8;
        tg[k][tx] = gp[(size_t)k * DHID + tx];
        tu[k][tx] = up[(size_t)k * DHID + tx];
    }
    __syncthreads();
#pragma unroll
    for (int i = 0; i < 4; ++i) {
        int hh = ty + i * 8;
        size_t row = ((size_t)g * 2 * DHID + 2 * (size_t)(h0 + hh)) * DIN + k0;
        g_wA[row + tx]       = __float2half(tg[tx][hh]);
        g_wA[row + DIN + tx] = __float2half(tu[tx][hh]);
    }
}

__global__ void prep_down(const float* __restrict__ dw) {
    __shared__ float t[32][33];
    int g = blockIdx.z, h0 = blockIdx.x * 32, o0 = blockIdx.y * 32;
    int tx = threadIdx.x, ty = threadIdx.y;
    const float* dp = dw + ((size_t)g * DHID + h0) * DOUT + o0;
#pragma unroll
    for (int i = 0; i < 4; ++i) {
        int h = ty + i * 8;
        t[h][tx] = dp[(size_t)h * DOUT + tx];
    }
    __syncthreads();
#pragma unroll
    for (int i = 0; i < 4; ++i) {
        int oo = ty + i * 8;
        g_wD[((size_t)g * DOUT + o0 + oo) * DHID + h0 + tx] = __float2half(t[tx][oo]);
    }
}

__global__ void prep_x(const float* __restrict__ x) {
    size_t i = (size_t)blockIdx.x * blockDim.x + threadIdx.x;
    float4 v = reinterpret_cast<const float4*>(x)[i];
    __half2 a = __floats2half2_rn(v.x, v.y);
    __half2 b = __floats2half2_rn(v.z, v.w);
    uint2 o;
    o.x = *reinterpret_cast<uint32_t*>(&a);
    o.y = *reinterpret_cast<uint32_t*>(&b);
    reinterpret_cast<uint2*>(g_x16)[i] = o;
}

// ---------------- GEMM ----------------
// CTA tile M=256 x N=256, 512 threads (16 warps, 4x4), warp tile 64x64.
// K-step 64, 3-stage cp.async pipeline, XOR-swizzled 128B smem rows.
#define A_BYTES   (256u * 128u)           // 32768
#define B_BYTES   (256u * 128u)           // 32768
#define STAGE_B   (A_BYTES + B_BYTES)     // 65536
#define SMEM_BYTES (3u * STAGE_B)         // 196608

static __device__ __forceinline__ void load_stage(uint32_t sb, int s,
        const __half* __restrict__ A, int lda,
        const __half* __restrict__ B, int ldb, int k0, int tid) {
    uint32_t abase = sb + (uint32_t)s * STAGE_B;
#pragma unroll
    for (int i = 0; i < 4; ++i) {                 // A: 256 rows x 8 chunks(16B)
        int id = tid + (i << 9);
        int r = id >> 3, c = id & 7;
        uint32_t dst = abase + (uint32_t)r * 128u + (uint32_t)(((c ^ (r & 7)) << 4));
        CP_ASYNC16(dst, A + (size_t)r * lda + k0 + c * 8);
    }
    uint32_t bbase = abase + A_BYTES;
#pragma unroll
    for (int i = 0; i < 4; ++i) {                 // B: 256 rows x 8 chunks
        int id = tid + (i << 9);
        int r = id >> 3, c = id & 7;
        uint32_t dst = bbase + (uint32_t)r * 128u + (uint32_t)(((c ^ (r & 7)) << 4));
        CP_ASYNC16(dst, B + (size_t)r * ldb + k0 + c * 8);
    }
}

template<bool PHASE1>
__global__ __launch_bounds__(512, 1) void gemm_kernel(float* __restrict__ outp) {
    constexpr int KTOT = PHASE1 ? DIN : DHID;
    constexpr int NC   = KTOT / 64;
    constexpr int LDA  = NG * KTOT;

    extern __shared__ __align__(1024) char smem[];
    uint32_t sb = smem_u32(smem);
    int tid  = threadIdx.x;
    int wid  = tid >> 5;
    int lane = tid & 31;
    int wm   = wid >> 2;          // 0..3  (64-row block)
    int wn   = wid & 3;           // 0..3  (64-col block)
    int m0   = blockIdx.x * 256;
    int g    = blockIdx.z;

    const __half* Abase = (PHASE1 ? g_x16 : g_hid)
                        + (size_t)m0 * LDA + (size_t)g * KTOT;
    const __half* Bbase = (PHASE1 ? g_wA : g_wD)
                        + (size_t)g * (PHASE1 ? (size_t)2 * DHID * DIN : (size_t)DOUT * DHID)
                        + (size_t)blockIdx.y * 256 * KTOT;

    // Precomputed swizzled ldmatrix offsets (relative to stage base):
    // addr = base + (pre ^ (ch<<4)), ch = K-chunk index 0..7
    uint32_t preA[4], preB[4];
    {
        int rsel = lane & 15;
        int hi   = (lane >> 4) << 4;      // +16B for upper half
#pragma unroll
        for (int mt = 0; mt < 4; ++mt) {
            int row = wm * 64 + mt * 16 + rsel;
            preA[mt] = (uint32_t)row * 128u + (uint32_t)(((row & 7) << 4) ^ hi);
        }
#pragma unroll
        for (int nt = 0; nt < 4; ++nt) {
            int row = wn * 64 + nt * 16 + rsel;
            preB[nt] = (uint32_t)row * 128u + (uint32_t)(((row & 7) << 4) ^ hi);
        }
    }

    float acc[4][8][4];
#pragma unroll
    for (int a = 0; a < 4; ++a)
#pragma unroll
        for (int b = 0; b < 8; ++b)
#pragma unroll
            for (int c = 0; c < 4; ++c) acc[a][b][c] = 0.f;

    load_stage(sb, 0, Abase, LDA, Bbase, KTOT, 0, tid);
    CP_COMMIT();
    load_stage(sb, 1, Abase, LDA, Bbase, KTOT, 64, tid);
    CP_COMMIT();

    int st = 0;
#pragma unroll 1
    for (int c = 0; c < NC; ++c) {
        CP_WAIT1();
        __syncthreads();
        uint32_t abase = sb + (uint32_t)st * STAGE_B;
        uint32_t bbase = abase + A_BYTES;

        if (c + 2 < NC) {
            int st2 = (st == 0) ? 2 : st - 1;
            load_stage(sb, st2, Abase, LDA, Bbase, KTOT, (c + 2) * 64, tid);
        }
        CP_COMMIT();

        uint32_t af[2][4][4], bf[2][4][4];
#pragma unroll
        for (int mt = 0; mt < 4; ++mt) ldsm4(af[0][mt], abase + (preA[mt] ^ 0u));
#pragma unroll
        for (int nt = 0; nt < 4; ++nt) ldsm4(bf[0][nt], bbase + (preB[nt] ^ 0u));
#pragma unroll
        for (int kk = 0; kk < 4; ++kk) {
            int cur = kk & 1;
            if (kk < 3) {
                uint32_t x = (uint32_t)((kk + 1) << 5);   // ch = 2*(kk+1) -> (ch<<4)
#pragma unroll
                for (int mt = 0; mt < 4; ++mt) ldsm4(af[cur ^ 1][mt], abase + (preA[mt] ^ x));
#pragma unroll
                for (int nt = 0; nt < 4; ++nt) ldsm4(bf[cur ^ 1][nt], bbase + (preB[nt] ^ x));
            }
#pragma unroll
            for (int mt = 0; mt < 4; ++mt)
#pragma unroll
                for (int n8 = 0; n8 < 8; ++n8)
                    mma16816(acc[mt][n8], af[cur][mt],
                             bf[cur][n8 >> 1][n8 & 1], bf[cur][n8 >> 1][2 + (n8 & 1)]);
        }
        st = (st == 2) ? 0 : st + 1;
    }

    // ---- epilogue ----
    if constexpr (PHASE1) {
        __syncthreads();
        __half* sh = reinterpret_cast<__half*>(smem);   // staging [256][136]
#pragma unroll
        for (int mt = 0; mt < 4; ++mt)
#pragma unroll
            for (int n8 = 0; n8 < 8; ++n8) {
                int r0 = wm * 64 + mt * 16 + (lane >> 2);
                int hl = wn * 32 + n8 * 4 + (lane & 3);
                float* cc = acc[mt][n8];
                float gv0 = cc[0], uv0 = cc[1];
                float gv1 = cc[2], uv1 = cc[3];
                float h0 = uv0 * gv0 / (1.f + __expf(-gv0));
                float h1 = uv1 * gv1 / (1.f + __expf(-gv1));
                sh[(size_t)r0 * 136 + hl]       = __float2half(h0);
                sh[(size_t)(r0 + 8) * 136 + hl] = __float2half(h1);
            }
        __syncthreads();
        __half* optr = g_hid + (size_t)m0 * (NG * DHID) + (size_t)g * DHID
                     + (size_t)blockIdx.y * 128;
#pragma unroll
        for (int p = 0; p < 8; ++p) {
            int row = (tid >> 4) + p * 32;
            int ch  = tid & 15;
            uint4 v = *reinterpret_cast<uint4*>(sh + (size_t)row * 136 + ch * 8);
            *reinterpret_cast<uint4*>(optr + (size_t)row * (NG * DHID) + ch * 8) = v;
        }
    } else {
#pragma unroll
        for (int mt = 0; mt < 4; ++mt)
#pragma unroll
            for (int n8 = 0; n8 < 8; ++n8) {
                int r0  = wm * 64 + mt * 16 + (lane >> 2);
                int col = blockIdx.y * 256 + wn * 64 + n8 * 8 + (lane & 3) * 2;
                float* cc = acc[mt][n8];
                float* p0 = outp + ((size_t)(m0 + r0) * NG + g) * DOUT + col;
                float* p1 = outp + ((size_t)(m0 + r0 + 8) * NG + g) * DOUT + col;
                *reinterpret_cast<float2*>(p0) = make_float2(cc[0], cc[1]);
                *reinterpret_cast<float2*>(p1) = make_float2(cc[2], cc[3]);
            }
    }
}

// ---------------- launch ----------------
extern "C" void kernel_launch(void* const* d_in, const int* in_sizes, int n_in,
                              void* d_out, int out_size) {
    (void)in_sizes; (void)n_in; (void)out_size;
    const float* x  = (const float*)d_in[0];
    const float* gw = (const float*)d_in[1];
    const float* uw = (const float*)d_in[2];
    const float* dw = (const float*)d_in[3];
    float* out = (float*)d_out;

    cudaFuncSetAttribute(gemm_kernel<true>,  cudaFuncAttributeMaxDynamicSharedMemorySize, SMEM_BYTES);
    cudaFuncSetAttribute(gemm_kernel<false>, cudaFuncAttributeMaxDynamicSharedMemorySize, SMEM_BYTES);

    dim3 tb32x8(32, 8);
    prep_gateup<<<dim3(DIN / 32, DHID / 32, NG), tb32x8>>>(gw, uw);
    prep_down<<<dim3(DHID / 32, DOUT / 32, NG), tb32x8>>>(dw);
    prep_x<<<65536, 256>>>(x);

    // GEMM1: grid 8 m-tiles x 16 n-tiles x 32 groups
    gemm_kernel<true><<<dim3(8, 16, NG), 512, SMEM_BYTES>>>(out);
    // GEMM2: grid 8 m-tiles x 4 n-tiles x 32 groups
    gemm_kernel<false><<<dim3(8, 4, NG), 512, SMEM_BYTES>>>(out);
}

// round 5
// speedup vs baseline: 1.0736x; 1.0736x over previous
#include <cuda_runtime.h>
#include <cuda_fp16.h>
#include <cstdint>

#define NTOK 2048
#define NG   32
#define DIN  1024
#define DHID 2048
#define DOUT 1024

// ---------------- scratch ----------------
__device__ __align__(1024) __half g_wA[(size_t)NG * 2 * DHID * DIN];   // [g][2h+s][k]  (s=0 gate, 1 up)
__device__ __align__(1024) __half g_wD[(size_t)NG * DOUT * DHID];      // [g][o][h]
__device__ __align__(1024) __half g_x16[(size_t)NTOK * NG * DIN];      // fp16 x
__device__ __align__(1024) __half g_hid[(size_t)NTOK * NG * DHID];     // fp16 hidden

// ---------------- PTX helpers ----------------
static __device__ __forceinline__ uint32_t smem_u32(const void* p) {
    uint32_t a;
    asm("{ .reg .u64 t; cvta.to.shared.u64 t, %1; cvt.u32.u64 %0, t; }" : "=r"(a) : "l"(p));
    return a;
}
#define CP_ASYNC16(dst, src) \
    asm volatile("cp.async.cg.shared.global [%0], [%1], 16;" :: "r"(dst), "l"(src))
#define CP_COMMIT() asm volatile("cp.async.commit_group;" ::: "memory")
#define CP_WAIT1()  asm volatile("cp.async.wait_group 1;" ::: "memory")

static __device__ __forceinline__ void ldsm4(uint32_t* r, uint32_t addr) {
    asm volatile("ldmatrix.sync.aligned.m8n8.x4.shared.b16 {%0,%1,%2,%3}, [%4];"
                 : "=r"(r[0]), "=r"(r[1]), "=r"(r[2]), "=r"(r[3]) : "r"(addr));
}
static __device__ __forceinline__ void mma16816(float* c, const uint32_t* a,
                                                uint32_t b0, uint32_t b1) {
    asm volatile(
        "mma.sync.aligned.m16n8k16.row.col.f32.f16.f16.f32 "
        "{%0,%1,%2,%3}, {%4,%5,%6,%7}, {%8,%9}, {%0,%1,%2,%3};"
        : "+f"(c[0]), "+f"(c[1]), "+f"(c[2]), "+f"(c[3])
        : "r"(a[0]), "r"(a[1]), "r"(a[2]), "r"(a[3]), "r"(b0), "r"(b1));
}

// ---------------- prepass kernels (unchanged, proven) ----------------
__global__ void prep_gateup(const float* __restrict__ gw, const float* __restrict__ uw) {
    __shared__ float tg[32][33];
    __shared__ float tu[32][33];
    int g = blockIdx.z, k0 = blockIdx.x * 32, h0 = blockIdx.y * 32;
    int tx = threadIdx.x, ty = threadIdx.y;
    const float* gp = gw + ((size_t)g * DIN + k0) * DHID + h0;
    const float* up = uw + ((size_t)g * DIN + k0) * DHID + h0;
#pragma unroll
    for (int i = 0; i < 4; ++i) {
        int k = ty + i * 8;
        tg[k][tx] = gp[(size_t)k * DHID + tx];
        tu[k][tx] = up[(size_t)k * DHID + tx];
    }
    __syncthreads();
#pragma unroll
    for (int i = 0; i < 4; ++i) {
        int hh = ty + i * 8;
        size_t row = ((size_t)g * 2 * DHID + 2 * (size_t)(h0 + hh)) * DIN + k0;
        g_wA[row + tx]       = __float2half(tg[tx][hh]);
        g_wA[row + DIN + tx] = __float2half(tu[tx][hh]);
    }
}

__global__ void prep_down(const float* __restrict__ dw) {
    __shared__ float t[32][33];
    int g = blockIdx.z, h0 = blockIdx.x * 32, o0 = blockIdx.y * 32;
    int tx = threadIdx.x, ty = threadIdx.y;
    const float* dp = dw + ((size_t)g * DHID + h0) * DOUT + o0;
#pragma unroll
    for (int i = 0; i < 4; ++i) {
        int h = ty + i * 8;
        t[h][tx] = dp[(size_t)h * DOUT + tx];
    }
    __syncthreads();
#pragma unroll
    for (int i = 0; i < 4; ++i) {
        int oo = ty + i * 8;
        g_wD[((size_t)g * DOUT + o0 + oo) * DHID + h0 + tx] = __float2half(t[tx][oo]);
    }
}

__global__ void prep_x(const float* __restrict__ x) {
    size_t i = (size_t)blockIdx.x * blockDim.x + threadIdx.x;
    float4 v = reinterpret_cast<const float4*>(x)[i];
    __half2 a = __floats2half2_rn(v.x, v.y);
    __half2 b = __floats2half2_rn(v.z, v.w);
    uint2 o;
    o.x = *reinterpret_cast<uint32_t*>(&a);
    o.y = *reinterpret_cast<uint32_t*>(&b);
    reinterpret_cast<uint2*>(g_x16)[i] = o;
}

// ---------------- GEMM ----------------
// CTA tile M=128 x N=256, 256 threads (8 warps, 2x4), warp tile 64x64.
// K-step 64, 2-stage cp.async pipeline, 2 CTAs/SM (smem 96KB, regs 208*256=53K<64K).
#define A_BYTES   (128u * 128u)           // 16384
#define B_BYTES   (256u * 128u)           // 32768
#define STAGE_B   (A_BYTES + B_BYTES)     // 49152
#define SMEM_BYTES (2u * STAGE_B)         // 98304

static __device__ __forceinline__ void load_stage(uint32_t sb, int s,
        const __half* __restrict__ A, int lda,
        const __half* __restrict__ B, int ldb, int k0, int tid) {
    uint32_t abase = sb + (uint32_t)s * STAGE_B;
#pragma unroll
    for (int i = 0; i < 4; ++i) {                 // A: 128 rows x 8 chunks(16B)
        int id = tid + (i << 8);
        int r = id >> 3, c = id & 7;
        uint32_t dst = abase + (uint32_t)r * 128u + (uint32_t)(((c ^ (r & 7)) << 4));
        CP_ASYNC16(dst, A + (size_t)r * lda + k0 + c * 8);
    }
    uint32_t bbase = abase + A_BYTES;
#pragma unroll
    for (int i = 0; i < 8; ++i) {                 // B: 256 rows x 8 chunks
        int id = tid + (i << 8);
        int r = id >> 3, c = id & 7;
        uint32_t dst = bbase + (uint32_t)r * 128u + (uint32_t)(((c ^ (r & 7)) << 4));
        CP_ASYNC16(dst, B + (size_t)r * ldb + k0 + c * 8);
    }
}

template<bool PHASE1>
__global__ __launch_bounds__(256, 2) void gemm_kernel(float* __restrict__ outp) {
    constexpr int KTOT = PHASE1 ? DIN : DHID;
    constexpr int NC   = KTOT / 64;
    constexpr int LDA  = NG * KTOT;

    extern __shared__ __align__(1024) char smem[];
    uint32_t sb = smem_u32(smem);
    int tid  = threadIdx.x;
    int wid  = tid >> 5;
    int lane = tid & 31;
    int wm   = wid >> 2;          // 0..1  (64-row block)
    int wn   = wid & 3;           // 0..3  (64-col block)
    int m0   = blockIdx.x * 128;
    int g    = blockIdx.z;

    const __half* Abase = (PHASE1 ? g_x16 : g_hid)
                        + (size_t)m0 * LDA + (size_t)g * KTOT;
    const __half* Bbase = (PHASE1 ? g_wA : g_wD)
                        + (size_t)g * (PHASE1 ? (size_t)2 * DHID * DIN : (size_t)DOUT * DHID)
                        + (size_t)blockIdx.y * 256 * KTOT;

    // Precomputed swizzled ldmatrix offsets: addr = stagebase + (pre ^ (ch<<4))
    uint32_t preA[4], preB[4];
    {
        int rsel = lane & 15;
        int hi   = (lane >> 4) << 4;
#pragma unroll
        for (int mt = 0; mt < 4; ++mt) {
            int row = wm * 64 + mt * 16 + rsel;
            preA[mt] = (uint32_t)row * 128u + (uint32_t)(((row & 7) << 4) ^ hi);
        }
#pragma unroll
        for (int nt = 0; nt < 4; ++nt) {
            int row = wn * 64 + nt * 16 + rsel;
            preB[nt] = (uint32_t)row * 128u + (uint32_t)(((row & 7) << 4) ^ hi);
        }
    }

    float acc[4][8][4];
#pragma unroll
    for (int a = 0; a < 4; ++a)
#pragma unroll
        for (int b = 0; b < 8; ++b)
#pragma unroll
            for (int c = 0; c < 4; ++c) acc[a][b][c] = 0.f;

    load_stage(sb, 0, Abase, LDA, Bbase, KTOT, 0, tid);
    CP_COMMIT();

#pragma unroll 1
    for (int c = 0; c < NC; ++c) {
        if (c + 1 < NC)
            load_stage(sb, (c + 1) & 1, Abase, LDA, Bbase, KTOT, (c + 1) * 64, tid);
        CP_COMMIT();
        CP_WAIT1();               // oldest group (stage c) landed
        __syncthreads();

        uint32_t abase = sb + (uint32_t)(c & 1) * STAGE_B;
        uint32_t bbase = abase + A_BYTES;

        uint32_t af[2][4][4], bf[2][4][4];
#pragma unroll
        for (int mt = 0; mt < 4; ++mt) ldsm4(af[0][mt], abase + preA[mt]);
#pragma unroll
        for (int nt = 0; nt < 4; ++nt) ldsm4(bf[0][nt], bbase + preB[nt]);
#pragma unroll
        for (int kk = 0; kk < 4; ++kk) {
            int cur = kk & 1;
            if (kk < 3) {
                uint32_t x = (uint32_t)((kk + 1) << 5);
#pragma unroll
                for (int mt = 0; mt < 4; ++mt) ldsm4(af[cur ^ 1][mt], abase + (preA[mt] ^ x));
#pragma unroll
                for (int nt = 0; nt < 4; ++nt) ldsm4(bf[cur ^ 1][nt], bbase + (preB[nt] ^ x));
            }
#pragma unroll
            for (int mt = 0; mt < 4; ++mt)
#pragma unroll
                for (int n8 = 0; n8 < 8; ++n8)
                    mma16816(acc[mt][n8], af[cur][mt],
                             bf[cur][n8 >> 1][n8 & 1], bf[cur][n8 >> 1][2 + (n8 & 1)]);
        }
        __syncthreads();          // protect buffer (c+2)&1 reuse by next iteration's load
    }

    // ---- epilogue ----
    if constexpr (PHASE1) {
        __half* sh = reinterpret_cast<__half*>(smem);   // staging [128][136]
#pragma unroll
        for (int mt = 0; mt < 4; ++mt)
#pragma unroll
            for (int n8 = 0; n8 < 8; ++n8) {
                int r0 = wm * 64 + mt * 16 + (lane >> 2);
                int hl = wn * 32 + n8 * 4 + (lane & 3);
                float* cc = acc[mt][n8];
                float gv0 = cc[0], uv0 = cc[1];
                float gv1 = cc[2], uv1 = cc[3];
                float h0 = uv0 * gv0 / (1.f + __expf(-gv0));
                float h1 = uv1 * gv1 / (1.f + __expf(-gv1));
                sh[(size_t)r0 * 136 + hl]       = __float2half(h0);
                sh[(size_t)(r0 + 8) * 136 + hl] = __float2half(h1);
            }
        __syncthreads();
        __half* optr = g_hid + (size_t)m0 * (NG * DHID) + (size_t)g * DHID
                     + (size_t)blockIdx.y * 128;
#pragma unroll
        for (int p = 0; p < 8; ++p) {
            int row = (tid >> 4) + p * 16;
            int ch  = tid & 15;
            uint4 v = *reinterpret_cast<uint4*>(sh + (size_t)row * 136 + ch * 8);
            *reinterpret_cast<uint4*>(optr + (size_t)row * (NG * DHID) + ch * 8) = v;
        }
    } else {
#pragma unroll
        for (int mt = 0; mt < 4; ++mt)
#pragma unroll
            for (int n8 = 0; n8 < 8; ++n8) {
                int r0  = wm * 64 + mt * 16 + (lane >> 2);
                int col = blockIdx.y * 256 + wn * 64 + n8 * 8 + (lane & 3) * 2;
                float* cc = acc[mt][n8];
                float* p0 = outp + ((size_t)(m0 + r0) * NG + g) * DOUT + col;
                float* p1 = outp + ((size_t)(m0 + r0 + 8) * NG + g) * DOUT + col;
                *reinterpret_cast<float2*>(p0) = make_float2(cc[0], cc[1]);
                *reinterpret_cast<float2*>(p1) = make_float2(cc[2], cc[3]);
            }
    }
}

// ---------------- launch ----------------
extern "C" void kernel_launch(void* const* d_in, const int* in_sizes, int n_in,
                              void* d_out, int out_size) {
    (void)in_sizes; (void)n_in; (void)out_size;
    const float* x  = (const float*)d_in[0];
    const float* gw = (const float*)d_in[1];
    const float* uw = (const float*)d_in[2];
    const float* dw = (const float*)d_in[3];
    float* out = (float*)d_out;

    cudaFuncSetAttribute(gemm_kernel<true>,  cudaFuncAttributeMaxDynamicSharedMemorySize, SMEM_BYTES);
    cudaFuncSetAttribute(gemm_kernel<false>, cudaFuncAttributeMaxDynamicSharedMemorySize, SMEM_BYTES);

    dim3 tb32x8(32, 8);
    prep_gateup<<<dim3(DIN / 32, DHID / 32, NG), tb32x8>>>(gw, uw);
    prep_down<<<dim3(DHID / 32, DOUT / 32, NG), tb32x8>>>(dw);
    prep_x<<<65536, 256>>>(x);

    // GEMM1: grid 16 m-tiles x 16 n-tiles x 32 groups
    gemm_kernel<true><<<dim3(16, 16, NG), 256, SMEM_BYTES>>>(out);
    // GEMM2: grid 16 m-tiles x 4 n-tiles x 32 groups
    gemm_kernel<false><<<dim3(16, 4, NG), 256, SMEM_BYTES>>>(out);
}

// round 6
// speedup vs baseline: 3.2126x; 2.9922x over previous
#include <cuda_runtime.h>
#include <cuda_fp16.h>
#include <cstdint>

#define NTOK 2048
#define NG   32
#define DIN  1024
#define DHID 2048
#define DOUT 1024

// ---------------- scratch ----------------
__device__ __align__(1024) __half g_wA[(size_t)NG * 2 * DHID * DIN];   // [g][2h+s][k]  (s=0 gate, 1 up)
__device__ __align__(1024) __half g_wD[(size_t)NG * DOUT * DHID];      // [g][o][h]
__device__ __align__(1024) __half g_x16[(size_t)NTOK * NG * DIN];      // fp16 x
__device__ __align__(1024) __half g_hid[(size_t)NTOK * NG * DHID];     // fp16 hidden

// ---------------- PTX helpers ----------------
static __device__ __forceinline__ uint32_t smem_u32(const void* p) {
    uint32_t a;
    asm("{ .reg .u64 t; cvta.to.shared.u64 t, %1; cvt.u32.u64 %0, t; }" : "=r"(a) : "l"(p));
    return a;
}
#define CP_ASYNC16(dst, src) \
    asm volatile("cp.async.cg.shared.global [%0], [%1], 16;" :: "r"(dst), "l"(src))
#define CP_COMMIT() asm volatile("cp.async.commit_group;" ::: "memory")
#define CP_WAIT1()  asm volatile("cp.async.wait_group 1;" ::: "memory")

static __device__ __forceinline__ void ldsm4(uint32_t* r, uint32_t addr) {
    asm volatile("ldmatrix.sync.aligned.m8n8.x4.shared.b16 {%0,%1,%2,%3}, [%4];"
                 : "=r"(r[0]), "=r"(r[1]), "=r"(r[2]), "=r"(r[3]) : "r"(addr));
}
static __device__ __forceinline__ void mma16816(float* c, const uint32_t* a,
                                                uint32_t b0, uint32_t b1) {
    asm volatile(
        "mma.sync.aligned.m16n8k16.row.col.f32.f16.f16.f32 "
        "{%0,%1,%2,%3}, {%4,%5,%6,%7}, {%8,%9}, {%0,%1,%2,%3};"
        : "+f"(c[0]), "+f"(c[1]), "+f"(c[2]), "+f"(c[3])
        : "r"(a[0]), "r"(a[1]), "r"(a[2]), "r"(a[3]), "r"(b0), "r"(b1));
}

// ---------------- prepass kernels (unchanged, proven) ----------------
__global__ void prep_gateup(const float* __restrict__ gw, const float* __restrict__ uw) {
    __shared__ float tg[32][33];
    __shared__ float tu[32][33];
    int g = blockIdx.z, k0 = blockIdx.x * 32, h0 = blockIdx.y * 32;
    int tx = threadIdx.x, ty = threadIdx.y;
    const float* gp = gw + ((size_t)g * DIN + k0) * DHID + h0;
    const float* up = uw + ((size_t)g * DIN + k0) * DHID + h0;
#pragma unroll
    for (int i = 0; i < 4; ++i) {
        int k = ty + i * 8;
        tg[k][tx] = gp[(size_t)k * DHID + tx];
        tu[k][tx] = up[(size_t)k * DHID + tx];
    }
    __syncthreads();
#pragma unroll
    for (int i = 0; i < 4; ++i) {
        int hh = ty + i * 8;
        size_t row = ((size_t)g * 2 * DHID + 2 * (size_t)(h0 + hh)) * DIN + k0;
        g_wA[row + tx]       = __float2half(tg[tx][hh]);
        g_wA[row + DIN + tx] = __float2half(tu[tx][hh]);
    }
}

__global__ void prep_down(const float* __restrict__ dw) {
    __shared__ float t[32][33];
    int g = blockIdx.z, h0 = blockIdx.x * 32, o0 = blockIdx.y * 32;
    int tx = threadIdx.x, ty = threadIdx.y;
    const float* dp = dw + ((size_t)g * DHID + h0) * DOUT + o0;
#pragma unroll
    for (int i = 0; i < 4; ++i) {
        int h = ty + i * 8;
        t[h][tx] = dp[(size_t)h * DOUT + tx];
    }
    __syncthreads();
#pragma unroll
    for (int i = 0; i < 4; ++i) {
        int oo = ty + i * 8;
        g_wD[((size_t)g * DOUT + o0 + oo) * DHID + h0 + tx] = __float2half(t[tx][oo]);
    }
}

__global__ void prep_x(const float* __restrict__ x) {
    size_t i = (size_t)blockIdx.x * blockDim.x + threadIdx.x;
    float4 v = reinterpret_cast<const float4*>(x)[i];
    __half2 a = __floats2half2_rn(v.x, v.y);
    __half2 b = __floats2half2_rn(v.z, v.w);
    uint2 o;
    o.x = *reinterpret_cast<uint32_t*>(&a);
    o.y = *reinterpret_cast<uint32_t*>(&b);
    reinterpret_cast<uint2*>(g_x16)[i] = o;
}

// ---------------- GEMM ----------------
// CTA tile M=128 x N=128, 256 threads (8 warps, 2x4), warp tile 64x32.
// K-step 64, 3-stage cp.async pipeline, 2 CTAs/SM.
// Reg budget: 64 acc + 24 frag + ~25 misc ~ 113 < 128 cap (64K regs / 512 thr).
#define A_BYTES   (128u * 128u)           // 16384
#define B_BYTES   (128u * 128u)           // 16384
#define STAGE_B   (A_BYTES + B_BYTES)     // 32768
#define SMEM_BYTES (3u * STAGE_B)         // 98304 per CTA -> 192KB for 2 CTAs

static __device__ __forceinline__ void load_stage(uint32_t sb, int s,
        const __half* __restrict__ A, int lda,
        const __half* __restrict__ B, int ldb, int k0, int tid) {
    uint32_t abase = sb + (uint32_t)s * STAGE_B;
#pragma unroll
    for (int i = 0; i < 4; ++i) {                 // A: 128 rows x 8 chunks(16B)
        int id = tid + (i << 8);
        int r = id >> 3, c = id & 7;
        uint32_t dst = abase + (uint32_t)r * 128u + (uint32_t)(((c ^ (r & 7)) << 4));
        CP_ASYNC16(dst, A + (size_t)r * lda + k0 + c * 8);
    }
    uint32_t bbase = abase + A_BYTES;
#pragma unroll
    for (int i = 0; i < 4; ++i) {                 // B: 128 rows x 8 chunks
        int id = tid + (i << 8);
        int r = id >> 3, c = id & 7;
        uint32_t dst = bbase + (uint32_t)r * 128u + (uint32_t)(((c ^ (r & 7)) << 4));
        CP_ASYNC16(dst, B + (size_t)r * ldb + k0 + c * 8);
    }
}

template<bool PHASE1>
__global__ __launch_bounds__(256, 2) void gemm_kernel(float* __restrict__ outp) {
    constexpr int KTOT = PHASE1 ? DIN : DHID;
    constexpr int NC   = KTOT / 64;
    constexpr int LDA  = NG * KTOT;

    extern __shared__ __align__(1024) char smem[];
    uint32_t sb = smem_u32(smem);
    int tid  = threadIdx.x;
    int wid  = tid >> 5;
    int lane = tid & 31;
    int wm   = wid >> 2;          // 0..1  (64-row block)
    int wn   = wid & 3;           // 0..3  (32-col block)
    int m0   = blockIdx.x * 128;
    int g    = blockIdx.z;

    const __half* Abase = (PHASE1 ? g_x16 : g_hid)
                        + (size_t)m0 * LDA + (size_t)g * KTOT;
    const __half* Bbase = (PHASE1 ? g_wA : g_wD)
                        + (size_t)g * (PHASE1 ? (size_t)2 * DHID * DIN : (size_t)DOUT * DHID)
                        + (size_t)blockIdx.y * 128 * KTOT;

    // Precomputed swizzled ldmatrix offsets: addr = stagebase + (pre ^ (ch<<4))
    uint32_t preA[4], preB[2];
    {
        int rsel = lane & 15;
        int hi   = (lane >> 4) << 4;
#pragma unroll
        for (int mt = 0; mt < 4; ++mt) {
            int row = wm * 64 + mt * 16 + rsel;
            preA[mt] = (uint32_t)row * 128u + (uint32_t)(((row & 7) << 4) ^ hi);
        }
#pragma unroll
        for (int nt = 0; nt < 2; ++nt) {
            int row = wn * 32 + nt * 16 + rsel;
            preB[nt] = (uint32_t)row * 128u + (uint32_t)(((row & 7) << 4) ^ hi);
        }
    }

    float acc[4][4][4];
#pragma unroll
    for (int a = 0; a < 4; ++a)
#pragma unroll
        for (int b = 0; b < 4; ++b)
#pragma unroll
            for (int c = 0; c < 4; ++c) acc[a][b][c] = 0.f;

    load_stage(sb, 0, Abase, LDA, Bbase, KTOT, 0, tid);
    CP_COMMIT();
    load_stage(sb, 1, Abase, LDA, Bbase, KTOT, 64, tid);
    CP_COMMIT();

    int st = 0;
#pragma unroll 1
    for (int c = 0; c < NC; ++c) {
        CP_WAIT1();
        __syncthreads();
        uint32_t abase = sb + (uint32_t)st * STAGE_B;
        uint32_t bbase = abase + A_BYTES;

        if (c + 2 < NC) {
            int st2 = (st == 0) ? 2 : st - 1;
            load_stage(sb, st2, Abase, LDA, Bbase, KTOT, (c + 2) * 64, tid);
        }
        CP_COMMIT();

#pragma unroll
        for (int kk = 0; kk < 4; ++kk) {
            uint32_t x = (uint32_t)(kk << 5);     // ch = 2*kk -> (ch<<4)
            uint32_t af[4][4], bf[2][4];
#pragma unroll
            for (int mt = 0; mt < 4; ++mt) ldsm4(af[mt], abase + (preA[mt] ^ x));
#pragma unroll
            for (int nt = 0; nt < 2; ++nt) ldsm4(bf[nt], bbase + (preB[nt] ^ x));
#pragma unroll
            for (int mt = 0; mt < 4; ++mt)
#pragma unroll
                for (int n8 = 0; n8 < 4; ++n8)
                    mma16816(acc[mt][n8], af[mt],
                             bf[n8 >> 1][n8 & 1], bf[n8 >> 1][2 + (n8 & 1)]);
        }
        st = (st == 2) ? 0 : st + 1;
    }

    // ---- epilogue ----
    if constexpr (PHASE1) {
        __syncthreads();
        __half* sh = reinterpret_cast<__half*>(smem);   // staging [128][72]
#pragma unroll
        for (int mt = 0; mt < 4; ++mt)
#pragma unroll
            for (int n8 = 0; n8 < 4; ++n8) {
                int r0 = wm * 64 + mt * 16 + (lane >> 2);
                int hl = wn * 16 + n8 * 4 + (lane & 3);
                float* cc = acc[mt][n8];
                float gv0 = cc[0], uv0 = cc[1];
                float gv1 = cc[2], uv1 = cc[3];
                float h0 = uv0 * gv0 / (1.f + __expf(-gv0));
                float h1 = uv1 * gv1 / (1.f + __expf(-gv1));
                sh[(size_t)r0 * 72 + hl]       = __float2half(h0);
                sh[(size_t)(r0 + 8) * 72 + hl] = __float2half(h1);
            }
        __syncthreads();
        // copy out: 128 rows x 64 halves
        __half* optr = g_hid + (size_t)m0 * (NG * DHID) + (size_t)g * DHID
                     + (size_t)blockIdx.y * 64;
#pragma unroll
        for (int p = 0; p < 4; ++p) {
            int row = (tid >> 3) + p * 32;
            int ch  = tid & 7;
            uint4 v = *reinterpret_cast<uint4*>(sh + (size_t)row * 72 + ch * 8);
            *reinterpret_cast<uint4*>(optr + (size_t)row * (NG * DHID) + ch * 8) = v;
        }
    } else {
#pragma unroll
        for (int mt = 0; mt < 4; ++mt)
#pragma unroll
            for (int n8 = 0; n8 < 4; ++n8) {
                int r0  = wm * 64 + mt * 16 + (lane >> 2);
                int col = blockIdx.y * 128 + wn * 32 + n8 * 8 + (lane & 3) * 2;
                float* cc = acc[mt][n8];
                float* p0 = outp + ((size_t)(m0 + r0) * NG + g) * DOUT + col;
                float* p1 = outp + ((size_t)(m0 + r0 + 8) * NG + g) * DOUT + col;
                *reinterpret_cast<float2*>(p0) = make_float2(cc[0], cc[1]);
                *reinterpret_cast<float2*>(p1) = make_float2(cc[2], cc[3]);
            }
    }
}

// ---------------- launch ----------------
extern "C" void kernel_launch(void* const* d_in, const int* in_sizes, int n_in,
                              void* d_out, int out_size) {
    (void)in_sizes; (void)n_in; (void)out_size;
    const float* x  = (const float*)d_in[0];
    const float* gw = (const float*)d_in[1];
    const float* uw = (const float*)d_in[2];
    const float* dw = (const float*)d_in[3];
    float* out = (float*)d_out;

    cudaFuncSetAttribute(gemm_kernel<true>,  cudaFuncAttributeMaxDynamicSharedMemorySize, SMEM_BYTES);
    cudaFuncSetAttribute(gemm_kernel<false>, cudaFuncAttributeMaxDynamicSharedMemorySize, SMEM_BYTES);

    dim3 tb32x8(32, 8);
    prep_gateup<<<dim3(DIN / 32, DHID / 32, NG), tb32x8>>>(gw, uw);
    prep_down<<<dim3(DHID / 32, DOUT / 32, NG), tb32x8>>>(dw);
    prep_x<<<65536, 256>>>(x);

    // GEMM1: grid 16 m-tiles x 32 n-tiles x 32 groups
    gemm_kernel<true><<<dim3(16, 32, NG), 256, SMEM_BYTES>>>(out);
    // GEMM2: grid 16 m-tiles x 8 n-tiles x 32 groups
    gemm_kernel<false><<<dim3(16, 8, NG), 256, SMEM_BYTES>>>(out);
}